// round 1
// baseline (speedup 1.0000x reference)
#include <cuda_runtime.h>
#include <math.h>

#define Bb 128
#define Ss 256
#define Ii 512
#define Oo 512
#define Hh 1024
#define Gg (3*Hh)      // 3072
#define IOio (Ii+Oo)   // 1024

// ---- output layout (concatenated, reference return order) ----
#define PROBS_OFF  0
#define PRE_OFF    ((size_t)Bb*Ss*Oo)                       // 16777216
#define SAMP_OFF   (PRE_OFF + (size_t)Bb*Ss*Hh)             // 50331648
#define HX_OFF     (SAMP_OFF + (size_t)Bb*Ss*Oo)            // 67108864

// ---- scratch (static device allocations are permitted) ----
__device__ int   g_idx[Bb*Ss];                         // one-hot target index per (s,b)
__device__ float g_gi[(size_t)Ss*Bb*Gg];               // [S,B,3H]  input-side gates
__device__ float g_h[Bb*Hh];                           // current hidden
__device__ float g_gh[Bb*Gg];                          // per-step hidden-side gates
__device__ float g_hs[(size_t)Bb*Ss*Hh];               // [B,S,H] hidden history
__device__ float g_logits[(size_t)Bb*Ss*Oo];           // [B,S,O]

// ============================================================
// 1) extract one-hot indices of teacher-forcing targets
//    row m = s*B + b ; s==0 -> gotoken, else groundTruth[b][s-1]
// ============================================================
__global__ void k_idx(const float* __restrict__ gt, const float* __restrict__ gotoken) {
    int wg   = (blockIdx.x * blockDim.x + threadIdx.x) >> 5;
    int lane = threadIdx.x & 31;
    if (wg >= Bb*Ss) return;
    int s = wg / Bb, b = wg % Bb;
    const float* src = (s == 0) ? gotoken : (gt + ((size_t)b*Ss + (s-1))*Oo);
    int found = Oo;
    for (int o = lane; o < Oo; o += 32)
        if (src[o] > 0.5f) found = min(found, o);
    #pragma unroll
    for (int off = 16; off; off >>= 1)
        found = min(found, __shfl_xor_sync(0xffffffffu, found, off));
    if (lane == 0) g_idx[wg] = found;
}

__global__ void k_copyh(const float* __restrict__ hx) {
    int i = blockIdx.x * blockDim.x + threadIdx.x;
    if (i < Bb*Hh) g_h[i] = hx[i];
}

// ============================================================
// 2) gi GEMM: M=32768 (m=s*B+b), N=3072, K=512 (y part only)
//    epilogue adds one-hot gather column + bias_ih
//    BM=128 (one s per tile), BN=64, BK=16, 256 thr, 8x4/thread
// ============================================================
__global__ __launch_bounds__(256) void k_gemm_gi(const float* __restrict__ y,
                                                 const float* __restrict__ wih,
                                                 const float* __restrict__ bih) {
    __shared__ float As[16][128+4];
    __shared__ float Bs[16][64+4];
    int s  = blockIdx.y;
    int n0 = blockIdx.x * 64;
    int tid = threadIdx.x;
    int tx = tid & 15, ty = tid >> 4;
    float acc[8][4] = {};
    int arow = tid >> 2;            // 0..63
    int acol = (tid & 3) * 4;
    for (int k0 = 0; k0 < Ii; k0 += 16) {
        #pragma unroll
        for (int hseg = 0; hseg < 2; hseg++) {
            int b = arow + hseg*64;
            float4 v = *(const float4*)(y + ((size_t)b*Ss + s)*Ii + k0 + acol);
            As[acol+0][b] = v.x; As[acol+1][b] = v.y; As[acol+2][b] = v.z; As[acol+3][b] = v.w;
        }
        {
            int gg = n0 + arow;
            float4 v = *(const float4*)(wih + (size_t)gg*IOio + k0 + acol);
            Bs[acol+0][arow] = v.x; Bs[acol+1][arow] = v.y; Bs[acol+2][arow] = v.z; Bs[acol+3][arow] = v.w;
        }
        __syncthreads();
        #pragma unroll
        for (int k = 0; k < 16; k++) {
            float ar[8], br[4];
            #pragma unroll
            for (int i2 = 0; i2 < 8; i2++) ar[i2] = As[k][ty*8+i2];
            #pragma unroll
            for (int j = 0; j < 4; j++)   br[j]  = Bs[k][tx*4+j];
            #pragma unroll
            for (int i2 = 0; i2 < 8; i2++)
                #pragma unroll
                for (int j = 0; j < 4; j++) acc[i2][j] += ar[i2]*br[j];
        }
        __syncthreads();
    }
    #pragma unroll
    for (int i2 = 0; i2 < 8; i2++) {
        int b = ty*8 + i2;
        int m = s*Bb + b;
        int id = g_idx[m];
        #pragma unroll
        for (int j = 0; j < 4; j++) {
            int gg = n0 + tx*4 + j;
            g_gi[(size_t)m*Gg + gg] = acc[i2][j] + wih[(size_t)gg*IOio + Ii + id] + bih[gg];
        }
    }
}

// ============================================================
// 3) per-step hidden GEMM: gh[b][g] = h[b,:] . W_hh[g,:] + bhh[g]
//    M=128, N=3072, K=1024 ; BM=64, BN=32, BK=16 -> 192 CTAs
// ============================================================
__global__ __launch_bounds__(256) void k_gemm_gh(const float* __restrict__ whh,
                                                 const float* __restrict__ bhh) {
    __shared__ float As[16][64+4];
    __shared__ float Bs[16][32+4];
    int m0 = blockIdx.y * 64;
    int n0 = blockIdx.x * 32;
    int tid = threadIdx.x;
    int tx = tid & 15, ty = tid >> 4;
    float acc[4][2] = {};
    int arow = tid >> 2, acol = (tid & 3) * 4;   // 64x16 A tile: 1 float4 each
    int brow = tid >> 3, bcol = (tid & 7) * 2;   // 32x16 B tile: 1 float2 each
    for (int k0 = 0; k0 < Hh; k0 += 16) {
        float4 va = *(const float4*)(g_h + (size_t)(m0+arow)*Hh + k0 + acol);
        As[acol+0][arow] = va.x; As[acol+1][arow] = va.y; As[acol+2][arow] = va.z; As[acol+3][arow] = va.w;
        float2 vb = *(const float2*)(whh + (size_t)(n0+brow)*Hh + k0 + bcol);
        Bs[bcol+0][brow] = vb.x; Bs[bcol+1][brow] = vb.y;
        __syncthreads();
        #pragma unroll
        for (int k = 0; k < 16; k++) {
            float ar[4], br[2];
            #pragma unroll
            for (int i2 = 0; i2 < 4; i2++) ar[i2] = As[k][ty*4+i2];
            br[0] = Bs[k][tx*2]; br[1] = Bs[k][tx*2+1];
            #pragma unroll
            for (int i2 = 0; i2 < 4; i2++) {
                acc[i2][0] += ar[i2]*br[0];
                acc[i2][1] += ar[i2]*br[1];
            }
        }
        __syncthreads();
    }
    #pragma unroll
    for (int i2 = 0; i2 < 4; i2++) {
        int mb = m0 + ty*4 + i2;
        #pragma unroll
        for (int j = 0; j < 2; j++) {
            int gg = n0 + tx*2 + j;
            g_gh[(size_t)mb*Gg + gg] = acc[i2][j] + bhh[gg];
        }
    }
}

// ============================================================
// 4) per-step GRU gate update
// ============================================================
__global__ __launch_bounds__(256) void k_update(int s, float* __restrict__ out_pre) {
    int i = blockIdx.x * blockDim.x + threadIdx.x;
    if (i >= Bb*Hh) return;
    int b = i / Hh, hh = i % Hh;
    size_t gib = ((size_t)(s*Bb + b))*Gg;
    float ir = g_gi[gib + hh];
    float iz = g_gi[gib + Hh + hh];
    float in_ = g_gi[gib + 2*Hh + hh];
    size_t ghb = (size_t)b*Gg;
    float hr = g_gh[ghb + hh];
    float hz = g_gh[ghb + Hh + hh];
    float hn = g_gh[ghb + 2*Hh + hh];
    float h  = g_h[i];
    float r  = 1.0f/(1.0f + expf(-(ir+hr)));
    float z  = 1.0f/(1.0f + expf(-(iz+hz)));
    float pre = in_ + r*hn;
    float n   = tanhf(pre);
    float hy  = n + z*(h - n);
    g_h[i] = hy;
    size_t om = ((size_t)b*Ss + s)*Hh + hh;
    g_hs[om]   = hy;
    out_pre[om] = pre;
}

// ============================================================
// 5) output head GEMM: logits[m][o], m=b*S+s ; M=32768,N=512,K=1024
// ============================================================
__global__ __launch_bounds__(256) void k_gemm_logits(const float* __restrict__ lw,
                                                     const float* __restrict__ lb) {
    __shared__ float As[16][128+4];
    __shared__ float Bs[16][64+4];
    int m0 = blockIdx.y * 128;
    int n0 = blockIdx.x * 64;
    int tid = threadIdx.x;
    int tx = tid & 15, ty = tid >> 4;
    float acc[8][4] = {};
    int arow = tid >> 2;
    int acol = (tid & 3) * 4;
    for (int k0 = 0; k0 < Hh; k0 += 16) {
        #pragma unroll
        for (int hseg = 0; hseg < 2; hseg++) {
            int r = arow + hseg*64;
            float4 v = *(const float4*)(g_hs + (size_t)(m0+r)*Hh + k0 + acol);
            As[acol+0][r] = v.x; As[acol+1][r] = v.y; As[acol+2][r] = v.z; As[acol+3][r] = v.w;
        }
        {
            int oo = n0 + arow;
            float4 v = *(const float4*)(lw + (size_t)oo*Hh + k0 + acol);
            Bs[acol+0][arow] = v.x; Bs[acol+1][arow] = v.y; Bs[acol+2][arow] = v.z; Bs[acol+3][arow] = v.w;
        }
        __syncthreads();
        #pragma unroll
        for (int k = 0; k < 16; k++) {
            float ar[8], br[4];
            #pragma unroll
            for (int i2 = 0; i2 < 8; i2++) ar[i2] = As[k][ty*8+i2];
            #pragma unroll
            for (int j = 0; j < 4; j++)   br[j]  = Bs[k][tx*4+j];
            #pragma unroll
            for (int i2 = 0; i2 < 8; i2++)
                #pragma unroll
                for (int j = 0; j < 4; j++) acc[i2][j] += ar[i2]*br[j];
        }
        __syncthreads();
    }
    #pragma unroll
    for (int i2 = 0; i2 < 8; i2++) {
        int m = m0 + ty*8 + i2;
        #pragma unroll
        for (int j = 0; j < 4; j++) {
            int oo = n0 + tx*4 + j;
            g_logits[(size_t)m*Oo + oo] = acc[i2][j] + lb[oo];
        }
    }
}

// ============================================================
// 6) softmax + argmax one-hot (probs & sampled_output)
// ============================================================
__global__ __launch_bounds__(128) void k_softmax(float* __restrict__ out) {
    int m = blockIdx.x;
    const float* lg = g_logits + (size_t)m*Oo;
    __shared__ float smax[128];
    __shared__ int   sidx[128];
    __shared__ float ssum[128];
    int t = threadIdx.x;
    float vmax = -1e30f; int vidx = 0;
    for (int o = t; o < Oo; o += 128) {
        float v = lg[o];
        if (v > vmax) { vmax = v; vidx = o; }
    }
    smax[t] = vmax; sidx[t] = vidx; __syncthreads();
    for (int off = 64; off; off >>= 1) {
        if (t < off) {
            if (smax[t+off] > smax[t] || (smax[t+off] == smax[t] && sidx[t+off] < sidx[t])) {
                smax[t] = smax[t+off]; sidx[t] = sidx[t+off];
            }
        }
        __syncthreads();
    }
    float rmax = smax[0]; int amax = sidx[0];
    float lsum = 0.f;
    for (int o = t; o < Oo; o += 128) lsum += expf(lg[o]-rmax);
    ssum[t] = lsum; __syncthreads();
    for (int off = 64; off; off >>= 1) {
        if (t < off) ssum[t] += ssum[t+off];
        __syncthreads();
    }
    float inv = 1.0f / ssum[0];
    float* probs = out + PROBS_OFF + (size_t)m*Oo;
    float* samp  = out + SAMP_OFF  + (size_t)m*Oo;
    for (int o = t; o < Oo; o += 128) {
        probs[o] = expf(lg[o]-rmax) * inv;
        samp[o]  = (o == amax) ? 1.0f : 0.0f;
    }
}

__global__ void k_hx(float* __restrict__ out) {
    int i = blockIdx.x * blockDim.x + threadIdx.x;
    if (i < Bb*Hh) out[i] = g_h[i];
}

// ============================================================
extern "C" void kernel_launch(void* const* d_in, const int* in_sizes, int n_in,
                              void* d_out, int out_size) {
    const float* y   = (const float*)d_in[0];
    const float* gt  = (const float*)d_in[1];
    const float* hx  = (const float*)d_in[2];
    const float* wih = (const float*)d_in[3];
    const float* bih = (const float*)d_in[4];
    const float* whh = (const float*)d_in[5];
    const float* bhh = (const float*)d_in[6];
    const float* lw  = (const float*)d_in[7];
    const float* lb  = (const float*)d_in[8];
    const float* got = (const float*)d_in[9];
    float* out = (float*)d_out;

    k_idx<<<(Bb*Ss)/8, 256>>>(gt, got);
    k_copyh<<<(Bb*Hh)/256, 256>>>(hx);
    k_gemm_gi<<<dim3(Gg/64, Ss), 256>>>(y, wih, bih);
    for (int s = 0; s < Ss; s++) {
        k_gemm_gh<<<dim3(Gg/32, Bb/64), 256>>>(whh, bhh);
        k_update<<<(Bb*Hh)/256, 256>>>(s, out + PRE_OFF);
    }
    k_gemm_logits<<<dim3(Oo/64, (Bb*Ss)/128), 256>>>(lw, lb);
    k_softmax<<<Bb*Ss, 128>>>(out);
    k_hx<<<(Bb*Hh+255)/256, 256>>>(out + HX_OFF);
}

// round 5
// speedup vs baseline: 1.4036x; 1.4036x over previous
#include <cuda_runtime.h>
#include <cuda_bf16.h>
#include <math.h>
#include <stdint.h>

#define Bb 128
#define Ss 256
#define Ii 512
#define Oo 512
#define Hh 1024
#define Gg (3*Hh)      // 3072
#define IOio (Ii+Oo)   // 1024

// ---- output layout ----
#define PROBS_OFF  0
#define PRE_OFF    ((size_t)Bb*Ss*Oo)
#define SAMP_OFF   (PRE_OFF + (size_t)Bb*Ss*Hh)
#define HX_OFF     (SAMP_OFF + (size_t)Bb*Ss*Oo)

// ---- scratch ----
__device__ int   g_idx[Bb*Ss];
__device__ float g_gi[(size_t)Ss*Bb*Gg];
__device__ float g_h[Bb*Hh];
__device__ float g_ghp[3][(size_t)Bb*Gg];     // split-K partials
__device__ float g_hs[(size_t)Bb*Ss*Hh];
__device__ float g_logits[(size_t)Bb*Ss*Oo];
// 3-way bf16 splits (h = h1+h2+h3, W = w1+w2+w3)
__device__ __nv_bfloat16 g_h1[Bb*Hh];
__device__ __nv_bfloat16 g_h2[Bb*Hh];
__device__ __nv_bfloat16 g_h3[Bb*Hh];
__device__ __nv_bfloat16 g_w1[(size_t)Gg*Hh];
__device__ __nv_bfloat16 g_w2[(size_t)Gg*Hh];
__device__ __nv_bfloat16 g_w3[(size_t)Gg*Hh];

// ============================================================
// PTX helpers (arch-generic: sm_80+ mma / ldmatrix / cp.async)
// ============================================================
__device__ __forceinline__ uint32_t smem_u32(const void* p) {
    uint32_t a;
    asm("{ .reg .u64 t; cvta.to.shared.u64 t, %1; cvt.u32.u64 %0, t; }" : "=r"(a) : "l"(p));
    return a;
}
__device__ __forceinline__ void cp16(uint32_t dst, const void* src) {
    asm volatile("cp.async.cg.shared.global [%0], [%1], 16;" :: "r"(dst), "l"(src));
}
#define CP_COMMIT() asm volatile("cp.async.commit_group;" ::: "memory")
#define CP_WAIT(n)  asm volatile("cp.async.wait_group %0;" :: "n"(n) : "memory")

__device__ __forceinline__ void ldmA(uint32_t* a, uint32_t addr) {
    asm volatile("ldmatrix.sync.aligned.m8n8.x4.shared.b16 {%0,%1,%2,%3}, [%4];"
        : "=r"(a[0]), "=r"(a[1]), "=r"(a[2]), "=r"(a[3]) : "r"(addr));
}
__device__ __forceinline__ void ldmB(uint32_t* b, uint32_t addr) {
    asm volatile("ldmatrix.sync.aligned.m8n8.x2.shared.b16 {%0,%1}, [%2];"
        : "=r"(b[0]), "=r"(b[1]) : "r"(addr));
}
__device__ __forceinline__ void mma_bf16(float* c, const uint32_t* a, const uint32_t* b) {
    asm volatile("mma.sync.aligned.m16n8k16.row.col.f32.bf16.bf16.f32 "
        "{%0,%1,%2,%3}, {%4,%5,%6,%7}, {%8,%9}, {%0,%1,%2,%3};"
        : "+f"(c[0]), "+f"(c[1]), "+f"(c[2]), "+f"(c[3])
        : "r"(a[0]), "r"(a[1]), "r"(a[2]), "r"(a[3]), "r"(b[0]), "r"(b[1]));
}

// product table: seg -> (A source, B source)
// 0:(h1,w1) 1:(h1,w2) 2:(h2,w1) 3:(h1,w3) 4:(h3,w1) 5:(h2,w2)
__device__ __forceinline__ const __nv_bfloat16* seg_a(int seg) {
    switch (seg) { case 2: case 5: return g_h2; case 4: return g_h3; default: return g_h1; }
}
__device__ __forceinline__ const __nv_bfloat16* seg_b(int seg) {
    switch (seg) { case 1: case 5: return g_w2; case 3: return g_w3; default: return g_w1; }
}

// ============================================================
// 1) one-hot indices of teacher-forcing targets
// ============================================================
__global__ void k_idx(const float* __restrict__ gt, const float* __restrict__ gotoken) {
    int wg   = (blockIdx.x * blockDim.x + threadIdx.x) >> 5;
    int lane = threadIdx.x & 31;
    if (wg >= Bb*Ss) return;
    int s = wg / Bb, b = wg % Bb;
    const float* src = (s == 0) ? gotoken : (gt + ((size_t)b*Ss + (s-1))*Oo);
    int found = Oo;
    for (int o = lane; o < Oo; o += 32)
        if (src[o] > 0.5f) found = min(found, o);
    #pragma unroll
    for (int off = 16; off; off >>= 1)
        found = min(found, __shfl_xor_sync(0xffffffffu, found, off));
    if (lane == 0) g_idx[wg] = found;
}

__device__ __forceinline__ void split3(float v, __nv_bfloat16& a, __nv_bfloat16& b, __nv_bfloat16& c) {
    a = __float2bfloat16(v);
    float r = v - __bfloat162float(a);
    b = __float2bfloat16(r);
    c = __float2bfloat16(r - __bfloat162float(b));
}

__global__ void k_copyh(const float* __restrict__ hx) {
    int i = blockIdx.x * blockDim.x + threadIdx.x;
    if (i < Bb*Hh) {
        float v = hx[i];
        g_h[i] = v;
        split3(v, g_h1[i], g_h2[i], g_h3[i]);
    }
}

__global__ void k_split_w(const float* __restrict__ w) {
    int i = blockIdx.x * blockDim.x + threadIdx.x;
    if (i < Gg*Hh) split3(w[i], g_w1[i], g_w2[i], g_w3[i]);
}

// ============================================================
// 2) gi GEMM (fp32): M=32768, N=3072, K=512 (one-hot gather epilogue)
// ============================================================
__global__ __launch_bounds__(256) void k_gemm_gi(const float* __restrict__ y,
                                                 const float* __restrict__ wih,
                                                 const float* __restrict__ bih) {
    __shared__ float As[16][128+4];
    __shared__ float Bs[16][64+4];
    int s  = blockIdx.y;
    int n0 = blockIdx.x * 64;
    int tid = threadIdx.x;
    int tx = tid & 15, ty = tid >> 4;
    float acc[8][4] = {};
    int arow = tid >> 2;
    int acol = (tid & 3) * 4;
    for (int k0 = 0; k0 < Ii; k0 += 16) {
        #pragma unroll
        for (int hseg = 0; hseg < 2; hseg++) {
            int b = arow + hseg*64;
            float4 v = *(const float4*)(y + ((size_t)b*Ss + s)*Ii + k0 + acol);
            As[acol+0][b] = v.x; As[acol+1][b] = v.y; As[acol+2][b] = v.z; As[acol+3][b] = v.w;
        }
        {
            int gg = n0 + arow;
            float4 v = *(const float4*)(wih + (size_t)gg*IOio + k0 + acol);
            Bs[acol+0][arow] = v.x; Bs[acol+1][arow] = v.y; Bs[acol+2][arow] = v.z; Bs[acol+3][arow] = v.w;
        }
        __syncthreads();
        #pragma unroll
        for (int k = 0; k < 16; k++) {
            float ar[8], br[4];
            #pragma unroll
            for (int i2 = 0; i2 < 8; i2++) ar[i2] = As[k][ty*8+i2];
            #pragma unroll
            for (int j = 0; j < 4; j++)   br[j]  = Bs[k][tx*4+j];
            #pragma unroll
            for (int i2 = 0; i2 < 8; i2++)
                #pragma unroll
                for (int j = 0; j < 4; j++) acc[i2][j] += ar[i2]*br[j];
        }
        __syncthreads();
    }
    #pragma unroll
    for (int i2 = 0; i2 < 8; i2++) {
        int b = ty*8 + i2;
        int m = s*Bb + b;
        int id = g_idx[m];
        #pragma unroll
        for (int j = 0; j < 4; j++) {
            int gg = n0 + tx*4 + j;
            g_gi[(size_t)m*Gg + gg] = acc[i2][j] + wih[(size_t)gg*IOio + Ii + id] + bih[gg];
        }
    }
}

// ============================================================
// 3) per-step hidden GEMM via mma.sync bf16, 3-way split (6 products)
//    K' = 6*1024 = 6144 -> 192 chunks of BK=32; split-K=3 over blockIdx.y
//    grid (48, 3): BM=128, BN=64, 8 warps (2M x 4N), warp tile 64x16
// ============================================================
#define STRD 80   // smem row stride in bytes (64B data = 32 bf16, +16B pad)

__global__ __launch_bounds__(256) void k_gemm_gh_mma() {
    __shared__ __align__(16) char Asm[2][128*STRD];
    __shared__ __align__(16) char Bsm[2][64*STRD];

    int tid  = threadIdx.x;
    int wid  = tid >> 5;
    int lane = tid & 31;
    int n0   = blockIdx.x * 64;
    int z    = blockIdx.y;          // split-K slice: chunks [z*64, z*64+64)
    int wm = (wid >> 2) * 64;
    int wn = (wid & 3) * 16;

    uint32_t aBase[2] = { smem_u32(Asm[0]), smem_u32(Asm[1]) };
    uint32_t bBase[2] = { smem_u32(Bsm[0]), smem_u32(Bsm[1]) };

    auto issue = [&](int c) {           // c in [0,64)
        int buf = c & 1;
        int cg  = z*64 + c;             // global chunk
        int seg = cg >> 5;              // 0..5
        int kl  = (cg & 31) << 5;       // k offset within segment
        const __nv_bfloat16* sa = seg_a(seg);
        const __nv_bfloat16* sb = seg_b(seg);
        #pragma unroll
        for (int i = 0; i < 2; i++) {
            int idx = i*256 + tid;
            int row = idx >> 2, q = idx & 3;
            cp16(aBase[buf] + row*STRD + q*16, sa + (size_t)row*Hh + kl + q*8);
        }
        {
            int row = tid >> 2, q = tid & 3;
            cp16(bBase[buf] + row*STRD + q*16, sb + (size_t)(n0 + row)*Hh + kl + q*8);
        }
    };

    float acc[4][2][4] = {};

    issue(0); CP_COMMIT();
    for (int c = 0; c < 64; c++) {
        if (c + 1 < 64) { issue(c + 1); CP_COMMIT(); CP_WAIT(1); }
        else            { CP_WAIT(0); }
        __syncthreads();
        int buf = c & 1;
        #pragma unroll
        for (int kk = 0; kk < 2; kk++) {
            uint32_t a[4][4], b[2][2];
            #pragma unroll
            for (int mt = 0; mt < 4; mt++) {
                uint32_t addr = aBase[buf] + (wm + mt*16 + (lane & 15))*STRD
                              + kk*32 + ((lane >> 4) & 1)*16;
                ldmA(a[mt], addr);
            }
            #pragma unroll
            for (int nt = 0; nt < 2; nt++) {
                uint32_t addr = bBase[buf] + (wn + nt*8 + (lane & 7))*STRD
                              + kk*32 + ((lane >> 3) & 1)*16;
                ldmB(b[nt], addr);
            }
            #pragma unroll
            for (int mt = 0; mt < 4; mt++)
                #pragma unroll
                for (int nt = 0; nt < 2; nt++)
                    mma_bf16(acc[mt][nt], a[mt], b[nt]);
        }
        __syncthreads();
    }

    // epilogue: write split-K partial
    float* dst = g_ghp[z];
    int quad = lane >> 2, tq = lane & 3;
    #pragma unroll
    for (int mt = 0; mt < 4; mt++) {
        #pragma unroll
        for (int nt = 0; nt < 2; nt++) {
            int row = wm + mt*16 + quad;
            int col = n0 + wn + nt*8 + tq*2;
            *(float2*)(dst + (size_t)row*Gg + col)     = make_float2(acc[mt][nt][0], acc[mt][nt][1]);
            *(float2*)(dst + (size_t)(row+8)*Gg + col) = make_float2(acc[mt][nt][2], acc[mt][nt][3]);
        }
    }
}

// ============================================================
// 4) per-step GRU gate update (sums partials, adds bias; emits 3-way h split)
// ============================================================
__global__ __launch_bounds__(256) void k_update(int s, const float* __restrict__ bhh,
                                                float* __restrict__ out_pre) {
    int i = blockIdx.x * blockDim.x + threadIdx.x;
    if (i >= Bb*Hh) return;
    int b = i / Hh, hh = i % Hh;
    size_t gib = ((size_t)(s*Bb + b))*Gg;
    float ir = g_gi[gib + hh];
    float iz = g_gi[gib + Hh + hh];
    float in_ = g_gi[gib + 2*Hh + hh];
    size_t ghb = (size_t)b*Gg;
    float hr = (g_ghp[0][ghb + hh]      + g_ghp[1][ghb + hh])      + g_ghp[2][ghb + hh]      + bhh[hh];
    float hz = (g_ghp[0][ghb + Hh + hh] + g_ghp[1][ghb + Hh + hh]) + g_ghp[2][ghb + Hh + hh] + bhh[Hh + hh];
    float hn = (g_ghp[0][ghb + 2*Hh+hh] + g_ghp[1][ghb + 2*Hh+hh]) + g_ghp[2][ghb + 2*Hh+hh] + bhh[2*Hh + hh];
    float h  = g_h[i];
    float r  = 1.0f/(1.0f + expf(-(ir+hr)));
    float z  = 1.0f/(1.0f + expf(-(iz+hz)));
    float pre = in_ + r*hn;
    float n   = tanhf(pre);
    float hy  = n + z*(h - n);
    g_h[i] = hy;
    split3(hy, g_h1[i], g_h2[i], g_h3[i]);
    size_t om = ((size_t)b*Ss + s)*Hh + hh;
    g_hs[om]   = hy;
    out_pre[om] = pre;
}

// ============================================================
// 5) output head GEMM (fp32): M=32768, N=512, K=1024
// ============================================================
__global__ __launch_bounds__(256) void k_gemm_logits(const float* __restrict__ lw,
                                                     const float* __restrict__ lb) {
    __shared__ float As[16][128+4];
    __shared__ float Bs[16][64+4];
    int m0 = blockIdx.y * 128;
    int n0 = blockIdx.x * 64;
    int tid = threadIdx.x;
    int tx = tid & 15, ty = tid >> 4;
    float acc[8][4] = {};
    int arow = tid >> 2;
    int acol = (tid & 3) * 4;
    for (int k0 = 0; k0 < Hh; k0 += 16) {
        #pragma unroll
        for (int hseg = 0; hseg < 2; hseg++) {
            int r = arow + hseg*64;
            float4 v = *(const float4*)(g_hs + (size_t)(m0+r)*Hh + k0 + acol);
            As[acol+0][r] = v.x; As[acol+1][r] = v.y; As[acol+2][r] = v.z; As[acol+3][r] = v.w;
        }
        {
            int oo = n0 + arow;
            float4 v = *(const float4*)(lw + (size_t)oo*Hh + k0 + acol);
            Bs[acol+0][arow] = v.x; Bs[acol+1][arow] = v.y; Bs[acol+2][arow] = v.z; Bs[acol+3][arow] = v.w;
        }
        __syncthreads();
        #pragma unroll
        for (int k = 0; k < 16; k++) {
            float ar[8], br[4];
            #pragma unroll
            for (int i2 = 0; i2 < 8; i2++) ar[i2] = As[k][ty*8+i2];
            #pragma unroll
            for (int j = 0; j < 4; j++)   br[j]  = Bs[k][tx*4+j];
            #pragma unroll
            for (int i2 = 0; i2 < 8; i2++)
                #pragma unroll
                for (int j = 0; j < 4; j++) acc[i2][j] += ar[i2]*br[j];
        }
        __syncthreads();
    }
    #pragma unroll
    for (int i2 = 0; i2 < 8; i2++) {
        int m = m0 + ty*8 + i2;
        #pragma unroll
        for (int j = 0; j < 4; j++) {
            int oo = n0 + tx*4 + j;
            g_logits[(size_t)m*Oo + oo] = acc[i2][j] + lb[oo];
        }
    }
}

// ============================================================
// 6) softmax + argmax one-hot
// ============================================================
__global__ __launch_bounds__(128) void k_softmax(float* __restrict__ out) {
    int m = blockIdx.x;
    const float* lg = g_logits + (size_t)m*Oo;
    __shared__ float smax[128];
    __shared__ int   sidx[128];
    __shared__ float ssum[128];
    int t = threadIdx.x;
    float vmax = -1e30f; int vidx = 0;
    for (int o = t; o < Oo; o += 128) {
        float v = lg[o];
        if (v > vmax) { vmax = v; vidx = o; }
    }
    smax[t] = vmax; sidx[t] = vidx; __syncthreads();
    for (int off = 64; off; off >>= 1) {
        if (t < off) {
            if (smax[t+off] > smax[t] || (smax[t+off] == smax[t] && sidx[t+off] < sidx[t])) {
                smax[t] = smax[t+off]; sidx[t] = sidx[t+off];
            }
        }
        __syncthreads();
    }
    float rmax = smax[0]; int amax = sidx[0];
    float lsum = 0.f;
    for (int o = t; o < Oo; o += 128) lsum += expf(lg[o]-rmax);
    ssum[t] = lsum; __syncthreads();
    for (int off = 64; off; off >>= 1) {
        if (t < off) ssum[t] += ssum[t+off];
        __syncthreads();
    }
    float inv = 1.0f / ssum[0];
    float* probs = out + PROBS_OFF + (size_t)m*Oo;
    float* samp  = out + SAMP_OFF  + (size_t)m*Oo;
    for (int o = t; o < Oo; o += 128) {
        probs[o] = expf(lg[o]-rmax) * inv;
        samp[o]  = (o == amax) ? 1.0f : 0.0f;
    }
}

__global__ void k_hx(float* __restrict__ out) {
    int i = blockIdx.x * blockDim.x + threadIdx.x;
    if (i < Bb*Hh) out[i] = g_h[i];
}

// ============================================================
extern "C" void kernel_launch(void* const* d_in, const int* in_sizes, int n_in,
                              void* d_out, int out_size) {
    const float* y   = (const float*)d_in[0];
    const float* gt  = (const float*)d_in[1];
    const float* hx  = (const float*)d_in[2];
    const float* wih = (const float*)d_in[3];
    const float* bih = (const float*)d_in[4];
    const float* whh = (const float*)d_in[5];
    const float* bhh = (const float*)d_in[6];
    const float* lw  = (const float*)d_in[7];
    const float* lb  = (const float*)d_in[8];
    const float* got = (const float*)d_in[9];
    float* out = (float*)d_out;

    k_idx<<<(Bb*Ss)/8, 256>>>(gt, got);
    k_split_w<<<(Gg*Hh)/256, 256>>>(whh);
    k_copyh<<<(Bb*Hh)/256, 256>>>(hx);
    k_gemm_gi<<<dim3(Gg/64, Ss), 256>>>(y, wih, bih);
    for (int s = 0; s < Ss; s++) {
        k_gemm_gh_mma<<<dim3(Gg/64, 3), 256>>>();
        k_update<<<(Bb*Hh)/256, 256>>>(s, bhh, out + PRE_OFF);
    }
    k_gemm_logits<<<dim3(Oo/64, (Bb*Ss)/128), 256>>>(lw, lb);
    k_softmax<<<Bb*Ss, 128>>>(out);
    k_hx<<<(Bb*Hh+255)/256, 256>>>(out + HX_OFF);
}